// round 3
// baseline (speedup 1.0000x reference)
#include <cuda_runtime.h>
#include <math.h>

#define NB   64
#define CCH  64
#define TT   300
#define VV   25
#define ICH  16
#define OCH  64
#define KTAP 9
#define TV   (TT*VV)        /* 7500 */
#define CTV  (CCH*TV)       /* 480000 */
#define NCTV (NB*CTV)       /* 30720000 */
#define BNEPS 1e-5f

typedef unsigned long long u64;
__device__ __forceinline__ u64 pk2(float lo, float hi) {
    u64 r; asm("mov.b64 %0,{%1,%2};" : "=l"(r) : "f"(lo), "f"(hi)); return r;
}
__device__ __forceinline__ void upk2(float& lo, float& hi, u64 v) {
    asm("mov.b64 {%0,%1},%2;" : "=f"(lo), "=f"(hi) : "l"(v));
}
__device__ __forceinline__ void fma2(u64& d, u64 a, u64 b) {
    asm("fma.rn.f32x2 %0,%1,%2,%3;" : "=l"(d) : "l"(a), "l"(b), "l"(d));
}

// ---------------- scratch (device globals; no allocation) ----------------
__device__ float g_fab[3*NB*32*TV];        // fa(16)+fb(16) per k,n
__device__ float g_Sp[3*NB*6*625];         // gram partials
__device__ float g_S[3*NB*VV*VV];          // attention matrices
__device__ float g_M[3*NB*OCH*TV];         // M = Wd[k] @ x
__device__ float g_y1[NB*OCH*TV];          // gcn pre-BN
__device__ float g_y3t[NB*OCH*TV];         // tcn output, [n][o][v][t] layout
__device__ float g_WtT[OCH*OCH*KTAP];      // Wt transposed: [(ic*9+kt)*64+o]
__device__ float g_pA_s[OCH*256];          // BN1 partials (sum)
__device__ float g_pA_q[OCH*256];          // BN1 partials (sumsq)
__device__ float g_pB_s[OCH*4800];         // BN2 partials
__device__ float g_pB_q[OCH*4800];
__device__ float g_stat[2*OCH*2];          // [which][o][{scale,shift}]

// ---------------- Wt transpose: [o][ic][kt] -> [(ic*9+kt)*64+o] ----------
__global__ void k_transpose_wt(const float* __restrict__ Wt)
{
    int j = blockIdx.x*256 + threadIdx.x;
    if (j >= OCH*OCH*KTAP) return;
    int o = j & 63;
    int r = j >> 6;
    int ic = r / 9, kt = r % 9;
    g_WtT[j] = Wt[(o*64 + ic)*9 + kt];
}

// ---------------- 1x1 conv producing fa (ch 0..15) and fb (16..31) -------
__global__ __launch_bounds__(256) void k_conv_fab(
    const float* __restrict__ x, const float* __restrict__ Wa,
    const float* __restrict__ ba, const float* __restrict__ Wb,
    const float* __restrict__ bb)
{
    int k = blockIdx.z, n = blockIdx.y;
    int pos = blockIdx.x * 256 + threadIdx.x;
    __shared__ float ws[64*36];          // transposed [c][j], pad 36 (16B-mult)
    __shared__ float bs[32];
    for (int i = threadIdx.x; i < 2048; i += 256) {
        int j = i >> 6, c = i & 63;
        float w = (j < 16) ? Wa[(k*16 + j)*64 + c] : Wb[(k*16 + (j-16))*64 + c];
        ws[c*36 + j] = w;
    }
    if (threadIdx.x < 32) {
        int j = threadIdx.x;
        bs[j] = (j < 16) ? ba[k*16 + j] : bb[k*16 + j - 16];
    }
    __syncthreads();
    if (pos >= TV) return;
    u64 acc2[16];
#pragma unroll
    for (int j = 0; j < 16; j++) acc2[j] = pk2(bs[2*j], bs[2*j+1]);
    const float* xp = x + n*CTV + pos;
    for (int c = 0; c < 64; c++) {
        float xv = xp[c*TV];
        u64 xq = pk2(xv, xv);
        const ulonglong2* wr = (const ulonglong2*)(ws + c*36);
#pragma unroll
        for (int j4 = 0; j4 < 8; j4++) {
            ulonglong2 w2 = wr[j4];
            fma2(acc2[2*j4+0], w2.x, xq);
            fma2(acc2[2*j4+1], w2.y, xq);
        }
    }
    float* op = g_fab + (k*NB + n)*32*TV + pos;
#pragma unroll
    for (int j = 0; j < 16; j++) {
        float a0, a1; upk2(a0, a1, acc2[j]);
        op[(2*j+0)*TV] = a0;
        op[(2*j+1)*TV] = a1;
    }
}

// ---------------- 1x1 conv producing M[k] = Wd[k] @ x ---------------------
__global__ __launch_bounds__(256) void k_conv_M(
    const float* __restrict__ x, const float* __restrict__ Wd)
{
    int k = blockIdx.z, n = blockIdx.y;
    int pos = blockIdx.x * 256 + threadIdx.x;
    __shared__ float ws[64*68];          // transposed [c][j], pad 68 (16B-mult)
    for (int i = threadIdx.x; i < 4096; i += 256) {
        int j = i >> 6, c = i & 63;
        ws[c*68 + j] = Wd[k*4096 + i];
    }
    __syncthreads();
    if (pos >= TV) return;
    u64 acc2[32];
#pragma unroll
    for (int j = 0; j < 32; j++) acc2[j] = 0ull;
    const float* xp = x + n*CTV + pos;
    for (int c = 0; c < 64; c++) {
        float xv = xp[c*TV];
        u64 xq = pk2(xv, xv);
        const ulonglong2* wr = (const ulonglong2*)(ws + c*68);
#pragma unroll
        for (int j4 = 0; j4 < 16; j4++) {
            ulonglong2 w2 = wr[j4];
            fma2(acc2[2*j4+0], w2.x, xq);
            fma2(acc2[2*j4+1], w2.y, xq);
        }
    }
    float* op = g_M + ((k*NB + n)*64)*TV + pos;
#pragma unroll
    for (int j = 0; j < 32; j++) {
        float a0, a1; upk2(a0, a1, acc2[j]);
        op[(2*j+0)*TV] = a0;
        op[(2*j+1)*TV] = a1;
    }
}

// ---------------- gram partial: 25x25 over (16 o, 50 t) per block ---------
__global__ __launch_bounds__(128) void k_gram_part()
{
    int n = blockIdx.x, k = blockIdx.y, tc = blockIdx.z;
    int t0 = tc * 50;
    int tid = threadIdx.x;
    __shared__ float fas[1250], fbs[1250];
    const float* fa = g_fab + (k*NB + n)*32*TV;
    const float* fb = fa + 16*TV;
    int v = tid / 5, wq = tid % 5;
    bool act = tid < 125;
    float acc[5] = {0.f, 0.f, 0.f, 0.f, 0.f};
    for (int o = 0; o < 16; o++) {
        for (int i = tid; i < 1250; i += 128) {
            fas[i] = fa[o*TV + t0*25 + i];
            fbs[i] = fb[o*TV + t0*25 + i];
        }
        __syncthreads();
        if (act) {
#pragma unroll 5
            for (int tt = 0; tt < 50; tt++) {
                float m = fas[tt*25 + v];
                const float* fr = fbs + tt*25 + wq*5;
#pragma unroll
                for (int j = 0; j < 5; j++) acc[j] += m * fr[j];
            }
        }
        __syncthreads();
    }
    if (act) {
        float* sp = g_Sp + ((k*NB + n)*6 + tc)*625 + v*25 + wq*5;
#pragma unroll
        for (int j = 0; j < 5; j++) sp[j] = acc[j];
    }
}

// ---------------- gram finalize: reduce partials + softmax + A ------------
__global__ __launch_bounds__(128) void k_gram_final(
    const float* __restrict__ adj, const float* __restrict__ PA)
{
    int n = blockIdx.x, k = blockIdx.y;
    int tid = threadIdx.x;
    __shared__ float Ss[625];
    const float* sp = g_Sp + (k*NB + n)*6*625;
    for (int i = tid; i < 625; i += 128) {
        float s = 0.f;
#pragma unroll
        for (int p = 0; p < 6; p++) s += sp[p*625 + i];
        Ss[i] = s * (1.f / 4800.f);
    }
    __syncthreads();
    if (tid < 25) {
        int ww = tid;
        float m = -1e30f;
        for (int vv = 0; vv < 25; vv++) m = fmaxf(m, Ss[vv*25 + ww]);
        float s = 0.f;
        for (int vv = 0; vv < 25; vv++) s += expf(Ss[vv*25 + ww] - m);
        float inv = 1.f / s;
        float* Sp = g_S + (k*NB + n)*625;
        for (int vv = 0; vv < 25; vv++)
            Sp[vv*25 + ww] = expf(Ss[vv*25 + ww] - m)*inv
                           + adj[k*625 + vv*25 + ww] + PA[k*625 + vv*25 + ww];
    }
}

// ---- y1[n,o,t,w] = sum_k sum_v M[k,n,o,t,v]*S[k,n,v,w] + bd (+BN1 part) --
__global__ __launch_bounds__(128) void k_combine(const float* __restrict__ bd)
{
    int tc = blockIdx.x, o = blockIdx.y, n = blockIdx.z;
    int t0 = tc * 75;
    __shared__ float Ms[3*1875];
    __shared__ float Ssh[3*625];
    __shared__ float red[256];
    int tid = threadIdx.x;
    for (int i = tid; i < 1875; i += 128) {
        int kk = i / 625, r = i % 625;
        Ssh[i] = g_S[(kk*NB + n)*625 + r];
    }
#pragma unroll
    for (int kk = 0; kk < 3; kk++)
        for (int i = tid; i < 1875; i += 128)
            Ms[kk*1875 + i] = g_M[((kk*NB + n)*64 + o)*TV + t0*25 + i];
    __syncthreads();
    float bds = bd[o] + bd[64 + o] + bd[128 + o];
    float acc[3][5];
    int wq = tid % 5, tq = tid / 5;
    int tb = tq * 3, wb = wq * 5;
    bool act = tid < 125;
#pragma unroll
    for (int i = 0; i < 3; i++)
#pragma unroll
        for (int j = 0; j < 5; j++) acc[i][j] = bds;
    if (act) {
#pragma unroll
        for (int kk = 0; kk < 3; kk++) {
            const float* Mb = Ms + kk*1875;
            const float* Sb = Ssh + kk*625;
            for (int vv = 0; vv < 25; vv++) {
                float m0 = Mb[(tb+0)*25 + vv];
                float m1 = Mb[(tb+1)*25 + vv];
                float m2 = Mb[(tb+2)*25 + vv];
                const float* sr = Sb + vv*25 + wb;
#pragma unroll
                for (int j = 0; j < 5; j++) {
                    float sv = sr[j];
                    acc[0][j] += m0 * sv;
                    acc[1][j] += m1 * sv;
                    acc[2][j] += m2 * sv;
                }
            }
        }
    }
    __syncthreads();
    if (act) {
#pragma unroll
        for (int i = 0; i < 3; i++)
#pragma unroll
            for (int j = 0; j < 5; j++)
                Ms[(tb+i)*25 + wb + j] = acc[i][j];
    }
    __syncthreads();
    float s = 0.f, s2 = 0.f;
    float* yp = g_y1 + (n*64 + o)*TV + t0*25;
    for (int i = tid; i < 1875; i += 128) {
        float u = Ms[i];
        yp[i] = u;
        s += u; s2 += u*u;
    }
    red[tid] = s; red[128 + tid] = s2;
    __syncthreads();
    for (int st = 64; st > 0; st >>= 1) {
        if (tid < st) {
            red[tid]       += red[tid + st];
            red[128 + tid] += red[128 + tid + st];
        }
        __syncthreads();
    }
    if (tid == 0) {
        g_pA_s[o*256 + n*4 + tc] = red[0];
        g_pA_q[o*256 + n*4 + tc] = red[128];
    }
}

// ---------------- BN finalize from partials -------------------------------
__global__ void k_bn_final(const float* __restrict__ g, const float* __restrict__ b,
                           const float* __restrict__ ps, const float* __restrict__ pq,
                           int npart, int which)
{
    int o = blockIdx.x;
    int tid = threadIdx.x;
    __shared__ float red[256];
    float s = 0.f, s2 = 0.f;
    for (int i = tid; i < npart; i += 128) {
        s  += ps[o*npart + i];
        s2 += pq[o*npart + i];
    }
    red[tid] = s; red[128 + tid] = s2;
    __syncthreads();
    for (int st = 64; st > 0; st >>= 1) {
        if (tid < st) {
            red[tid]       += red[tid + st];
            red[128 + tid] += red[128 + tid + st];
        }
        __syncthreads();
    }
    if (tid == 0) {
        const float cnt = (float)(NB*TV);
        float mean = red[0] / cnt;
        float var  = red[128] / cnt - mean*mean;
        float sc = g[o] * rsqrtf(var + BNEPS);
        g_stat[which*128 + o*2 + 0] = sc;
        g_stat[which*128 + o*2 + 1] = b[o] - mean*sc;
    }
}

// ---- tcn (FFMA2): y3t = Wt (*) relu(bn1(y1)+x) + bt ; transposed out ----
// grid (vc=5, tcb=15, n=64) block 320 = 64 o x 5 vs
__global__ __launch_bounds__(320, 2) void k_tcn2(
    const float* __restrict__ x, const float* __restrict__ bt)
{
    __shared__ float wsm[4*9*64];     // 2304
    __shared__ float ysm[4*28*5];     // 560
    __shared__ float red[640];
    int tid = threadIdx.x;
    int o  = tid & 63;
    int vs = tid >> 6;
    int vcb = blockIdx.x, tcb = blockIdx.y, n = blockIdx.z;
    int t0 = tcb * 20;
    int v  = vcb * 5 + vs;
    u64 accp[10];
#pragma unroll
    for (int p = 0; p < 10; p++) accp[p] = 0ull;

    for (int ch = 0; ch < 16; ch++) {
        for (int i = tid; i < 2304; i += 320)
            wsm[i] = g_WtT[ch*2304 + i];
        for (int i = tid; i < 560; i += 320) {
            int il = i / 140, r = i % 140;
            int tt = r / 5, vv = r % 5;
            int tg = t0 + tt - 4;
            int cin = ch*4 + il;
            float val = 0.f;
            if (tg >= 0 && tg < TT) {
                int idx = (n*64 + cin)*TV + tg*25 + vcb*5 + vv;
                float sc = g_stat[cin*2 + 0];
                float sf = g_stat[cin*2 + 1];
                val = fmaxf(0.f, g_y1[idx]*sc + sf + x[idx]);
            }
            ysm[(il*28 + tt)*5 + vv] = val;
        }
        __syncthreads();
#pragma unroll
        for (int il = 0; il < 4; il++) {
            float w[9];
#pragma unroll
            for (int kt = 0; kt < 9; kt++)
                w[kt] = wsm[(il*9 + kt)*64 + o];
            // wrev[j] = pack(w[j], w[j-1]); zero-padded ends
            u64 wrev[10];
#pragma unroll
            for (int j = 0; j < 10; j++) {
                float lo = (j < 9) ? w[j] : 0.f;
                float hi = (j >= 1) ? w[j-1] : 0.f;
                wrev[j] = pk2(lo, hi);
            }
#pragma unroll
            for (int tt = 0; tt < 28; tt++) {
                float yv = ysm[(il*28 + tt)*5 + vs];
                u64 yp = pk2(yv, yv);
#pragma unroll
                for (int p = 0; p < 10; p++) {
                    int j = tt - 2*p;
                    if (j >= 0 && j < 10)
                        fma2(accp[p], wrev[j], yp);
                }
            }
        }
        __syncthreads();
    }
    // epilogue: unpack, bias, partials, transposed store (t-contiguous)
    float acc[20];
#pragma unroll
    for (int p = 0; p < 10; p++) upk2(acc[2*p], acc[2*p+1], accp[p]);
    float bv = bt[o];
    float s = 0.f, s2 = 0.f;
#pragma unroll
    for (int t = 0; t < 20; t++) {
        acc[t] += bv;
        s += acc[t]; s2 += acc[t]*acc[t];
    }
    float* yp = g_y3t + (n*64 + o)*TV + v*TT + t0;
#pragma unroll
    for (int t4 = 0; t4 < 5; t4++) {
        float4 st4 = make_float4(acc[t4*4+0], acc[t4*4+1], acc[t4*4+2], acc[t4*4+3]);
        *(float4*)(yp + t4*4) = st4;
    }
    red[tid] = s; red[320 + tid] = s2;
    __syncthreads();
    if (tid < 64) {
        float ss = 0.f, qq = 0.f;
#pragma unroll
        for (int k = 0; k < 5; k++) {
            ss += red[tid + 64*k];
            qq += red[320 + tid + 64*k];
        }
        int p = (n*15 + tcb)*5 + vcb;
        g_pB_s[tid*4800 + p] = ss;
        g_pB_q[tid*4800 + p] = qq;
    }
}

// ---- final: out = relu(bn2(y3t) + x), reading transposed y3 -------------
__global__ __launch_bounds__(256) void k_bn_apply_t(
    const float* __restrict__ x, float* __restrict__ out)
{
    __shared__ float sm[25*301];
    int n = blockIdx.x, o = blockIdx.y;
    int tid = threadIdx.x;
    int base = (n*64 + o)*TV;
    for (int i = tid; i < TV; i += 256) {
        int v = i / 300, t = i % 300;
        sm[v*301 + t] = g_y3t[base + i];
    }
    __syncthreads();
    float sc = g_stat[128 + o*2 + 0];
    float sf = g_stat[128 + o*2 + 1];
    for (int i = tid; i < TV; i += 256) {
        int t = i / 25, v = i % 25;
        out[base + i] = fmaxf(0.f, sm[v*301 + t]*sc + sf + x[base + i]);
    }
}

// ---------------- launch --------------------------------------------------
extern "C" void kernel_launch(void* const* d_in, const int* in_sizes, int n_in,
                              void* d_out, int out_size)
{
    const float* x    = (const float*)d_in[0];
    const float* adj  = (const float*)d_in[1];
    const float* PA   = (const float*)d_in[2];
    const float* Wa   = (const float*)d_in[3];
    const float* ba   = (const float*)d_in[4];
    const float* Wb   = (const float*)d_in[5];
    const float* bb   = (const float*)d_in[6];
    const float* Wd   = (const float*)d_in[7];
    const float* bd   = (const float*)d_in[8];
    const float* g1   = (const float*)d_in[9];
    const float* b1   = (const float*)d_in[10];
    const float* Wt   = (const float*)d_in[11];
    const float* bt   = (const float*)d_in[12];
    const float* g2   = (const float*)d_in[13];
    const float* b2   = (const float*)d_in[14];
    float* out = (float*)d_out;

    float *pAs, *pAq, *pBs, *pBq;
    cudaGetSymbolAddress((void**)&pAs, g_pA_s);
    cudaGetSymbolAddress((void**)&pAq, g_pA_q);
    cudaGetSymbolAddress((void**)&pBs, g_pB_s);
    cudaGetSymbolAddress((void**)&pBq, g_pB_q);

    k_transpose_wt<<<144, 256>>>(Wt);

    dim3 gconv(30, NB, 3);
    k_conv_fab<<<gconv, 256>>>(x, Wa, ba, Wb, bb);
    k_conv_M<<<gconv, 256>>>(x, Wd);
    k_gram_part<<<dim3(NB, 3, 6), 128>>>();
    k_gram_final<<<dim3(NB, 3), 128>>>(adj, PA);
    k_combine<<<dim3(4, OCH, NB), 128>>>(bd);

    k_bn_final<<<64, 128>>>(g1, b1, pAs, pAq, 256, 0);

    k_tcn2<<<dim3(5, 15, NB), 320>>>(x, bt);

    k_bn_final<<<64, 128>>>(g2, b2, pBs, pBq, 4800, 1);

    k_bn_apply_t<<<dim3(NB, OCH), 256>>>(x, out);

    // second tuple element: adj_mat passthrough
    long tail = (long)out_size - (long)NCTV;
    if (tail > 0) {
        long cnt = tail < 1875 ? tail : 1875;
        cudaMemcpyAsync(out + NCTV, d_in[1], cnt * sizeof(float),
                        cudaMemcpyDeviceToDevice);
    }
}

// round 5
// speedup vs baseline: 1.3730x; 1.3730x over previous
#include <cuda_runtime.h>
#include <math.h>
#include <stdint.h>

#define NB   64
#define CCH  64
#define TT   300
#define VV   25
#define ICH  16
#define OCH  64
#define KTAP 9
#define TV   (TT*VV)        /* 7500 */
#define CTV  (CCH*TV)       /* 480000 */
#define NCTV (NB*CTV)       /* 30720000 */
#define BNEPS 1e-5f

#define TILE_P 128
#define NTILE  59           /* ceil(7500/128) */
#define NCTA_B (NB*NTILE)   /* 3776 */
#define YW 328              /* halo width: 128 + 2*100 ; 328%32==8 -> cf LDS */
#define SOW 130

__device__ __forceinline__ float tf32r(float v) {
    float o; asm("cvt.rna.tf32.f32 %0, %1;" : "=f"(o) : "f"(v)); return o;
}
__device__ __forceinline__ void mma_tf32(float c[4], uint32_t a0, uint32_t a1,
                                         uint32_t a2, uint32_t a3,
                                         uint32_t b0, uint32_t b1) {
    asm volatile(
        "mma.sync.aligned.m16n8k8.row.col.f32.tf32.tf32.f32 "
        "{%0,%1,%2,%3}, {%4,%5,%6,%7}, {%8,%9}, {%0,%1,%2,%3};"
        : "+f"(c[0]), "+f"(c[1]), "+f"(c[2]), "+f"(c[3])
        : "r"(a0), "r"(a1), "r"(a2), "r"(a3), "r"(b0), "r"(b1));
}

// ---------------- scratch (device globals; no allocation) ----------------
__device__ float g_fab[3*NB*32*TV];        // fa(16)+fb(16) per k,n
__device__ float g_Sp[3*NB*6*625];         // gram partials
__device__ float g_S[3*NB*VV*VV];          // attention matrices
__device__ float g_M[3*NB*OCH*TV];         // M = Wd[k] @ x
__device__ float g_y1[NB*OCH*TV];          // gcn pre-BN
__device__ float g_y3[NB*OCH*TV];          // tcn output
__device__ float g_Wf[9*8*8*32*2];         // packed tf32 B fragments
__device__ float g_pA_s[OCH*256];          // BN1 partials
__device__ float g_pA_q[OCH*256];
__device__ float g_pB_s[OCH*NCTA_B];       // BN2 partials
__device__ float g_pB_q[OCH*NCTA_B];
__device__ float g_stat[2*OCH*2];          // [which][o][{scale,shift}]

// ---- Wt -> per-lane packed tf32 B fragments: [kt][s][nt][lane][2] -------
__global__ void k_prep_wt(const float* __restrict__ Wt)
{
    int j = blockIdx.x*256 + threadIdx.x;
    if (j >= 9*8*8*32) return;
    int l  = j & 31;
    int nt = (j >> 5) & 7;
    int s  = (j >> 8) & 7;
    int kt = j >> 11;
    int cin = s*8 + (l & 3);
    int o   = nt*8 + (l >> 2);
    g_Wf[j*2 + 0] = tf32r(Wt[(o*64 + cin)*9 + kt]);
    g_Wf[j*2 + 1] = tf32r(Wt[(o*64 + cin + 4)*9 + kt]);
}

// ---------------- 1x1 conv producing fa (ch 0..15) and fb (16..31) -------
__global__ __launch_bounds__(256) void k_conv_fab(
    const float* __restrict__ x, const float* __restrict__ Wa,
    const float* __restrict__ ba, const float* __restrict__ Wb,
    const float* __restrict__ bb)
{
    int k = blockIdx.z, n = blockIdx.y;
    int pos = blockIdx.x * 256 + threadIdx.x;
    __shared__ float ws[64*36];
    __shared__ float bs[32];
    for (int i = threadIdx.x; i < 2048; i += 256) {
        int j = i >> 6, c = i & 63;
        float w = (j < 16) ? Wa[(k*16 + j)*64 + c] : Wb[(k*16 + (j-16))*64 + c];
        ws[c*36 + j] = w;
    }
    if (threadIdx.x < 32) {
        int j = threadIdx.x;
        bs[j] = (j < 16) ? ba[k*16 + j] : bb[k*16 + j - 16];
    }
    __syncthreads();
    if (pos >= TV) return;
    float acc[32];
#pragma unroll
    for (int j = 0; j < 32; j++) acc[j] = bs[j];
    const float* xp = x + n*CTV + pos;
    for (int c = 0; c < 64; c++) {
        float xv = xp[c*TV];
        const float4* wr = (const float4*)(ws + c*36);
#pragma unroll
        for (int j4 = 0; j4 < 8; j4++) {
            float4 w = wr[j4];
            acc[j4*4+0] += w.x * xv;
            acc[j4*4+1] += w.y * xv;
            acc[j4*4+2] += w.z * xv;
            acc[j4*4+3] += w.w * xv;
        }
    }
    float* op = g_fab + (k*NB + n)*32*TV + pos;
#pragma unroll
    for (int j = 0; j < 32; j++) op[j*TV] = acc[j];
}

// ---------------- 1x1 conv producing M[k] = Wd[k] @ x ---------------------
__global__ __launch_bounds__(256) void k_conv_M(
    const float* __restrict__ x, const float* __restrict__ Wd)
{
    int k = blockIdx.z, n = blockIdx.y;
    int pos = blockIdx.x * 256 + threadIdx.x;
    __shared__ float ws[64*68];
    for (int i = threadIdx.x; i < 4096; i += 256) {
        int j = i >> 6, c = i & 63;
        ws[c*68 + j] = Wd[k*4096 + i];
    }
    __syncthreads();
    if (pos >= TV) return;
    float acc[64];
#pragma unroll
    for (int j = 0; j < 64; j++) acc[j] = 0.f;
    const float* xp = x + n*CTV + pos;
    for (int c = 0; c < 64; c++) {
        float xv = xp[c*TV];
        const float4* wr = (const float4*)(ws + c*68);
#pragma unroll
        for (int j4 = 0; j4 < 16; j4++) {
            float4 w = wr[j4];
            acc[j4*4+0] += w.x * xv;
            acc[j4*4+1] += w.y * xv;
            acc[j4*4+2] += w.z * xv;
            acc[j4*4+3] += w.w * xv;
        }
    }
    float* op = g_M + ((k*NB + n)*64)*TV + pos;
#pragma unroll
    for (int j = 0; j < 64; j++) op[j*TV] = acc[j];
}

// ---------------- gram partial: 25x25 over (16 o, 50 t) per block ---------
__global__ __launch_bounds__(128) void k_gram_part()
{
    int n = blockIdx.x, k = blockIdx.y, tc = blockIdx.z;
    int t0 = tc * 50;
    int tid = threadIdx.x;
    __shared__ float fas[1250], fbs[1250];
    const float* fa = g_fab + (k*NB + n)*32*TV;
    const float* fb = fa + 16*TV;
    int v = tid / 5, wq = tid % 5;
    bool act = tid < 125;
    float acc[5] = {0.f, 0.f, 0.f, 0.f, 0.f};
    for (int o = 0; o < 16; o++) {
        for (int i = tid; i < 1250; i += 128) {
            fas[i] = fa[o*TV + t0*25 + i];
            fbs[i] = fb[o*TV + t0*25 + i];
        }
        __syncthreads();
        if (act) {
#pragma unroll 5
            for (int tt = 0; tt < 50; tt++) {
                float m = fas[tt*25 + v];
                const float* fr = fbs + tt*25 + wq*5;
#pragma unroll
                for (int j = 0; j < 5; j++) acc[j] += m * fr[j];
            }
        }
        __syncthreads();
    }
    if (act) {
        float* sp = g_Sp + ((k*NB + n)*6 + tc)*625 + v*25 + wq*5;
#pragma unroll
        for (int j = 0; j < 5; j++) sp[j] = acc[j];
    }
}

// ---------------- gram finalize: reduce partials + softmax + A ------------
__global__ __launch_bounds__(128) void k_gram_final(
    const float* __restrict__ adj, const float* __restrict__ PA)
{
    int n = blockIdx.x, k = blockIdx.y;
    int tid = threadIdx.x;
    __shared__ float Ss[625];
    const float* sp = g_Sp + (k*NB + n)*6*625;
    for (int i = tid; i < 625; i += 128) {
        float s = 0.f;
#pragma unroll
        for (int p = 0; p < 6; p++) s += sp[p*625 + i];
        Ss[i] = s * (1.f / 4800.f);
    }
    __syncthreads();
    if (tid < 25) {
        int ww = tid;
        float m = -1e30f;
        for (int vv = 0; vv < 25; vv++) m = fmaxf(m, Ss[vv*25 + ww]);
        float s = 0.f;
        for (int vv = 0; vv < 25; vv++) s += expf(Ss[vv*25 + ww] - m);
        float inv = 1.f / s;
        float* Sp = g_S + (k*NB + n)*625;
        for (int vv = 0; vv < 25; vv++)
            Sp[vv*25 + ww] = expf(Ss[vv*25 + ww] - m)*inv
                           + adj[k*625 + vv*25 + ww] + PA[k*625 + vv*25 + ww];
    }
}

// ---- y1 = sum_k sum_v M*S + bd (+BN1 partials) ---------------------------
__global__ __launch_bounds__(128) void k_combine(const float* __restrict__ bd)
{
    int tc = blockIdx.x, o = blockIdx.y, n = blockIdx.z;
    int t0 = tc * 75;
    __shared__ float Ms[3*1875];
    __shared__ float Ssh[3*625];
    __shared__ float red[256];
    int tid = threadIdx.x;
    for (int i = tid; i < 1875; i += 128) {
        int kk = i / 625, r = i % 625;
        Ssh[i] = g_S[(kk*NB + n)*625 + r];
    }
#pragma unroll
    for (int kk = 0; kk < 3; kk++)
        for (int i = tid; i < 1875; i += 128)
            Ms[kk*1875 + i] = g_M[((kk*NB + n)*64 + o)*TV + t0*25 + i];
    __syncthreads();
    float bds = bd[o] + bd[64 + o] + bd[128 + o];
    float acc[3][5];
    int wq = tid % 5, tq = tid / 5;
    int tb = tq * 3, wb = wq * 5;
    bool act = tid < 125;
#pragma unroll
    for (int i = 0; i < 3; i++)
#pragma unroll
        for (int j = 0; j < 5; j++) acc[i][j] = bds;
    if (act) {
#pragma unroll
        for (int kk = 0; kk < 3; kk++) {
            const float* Mb = Ms + kk*1875;
            const float* Sb = Ssh + kk*625;
            for (int vv = 0; vv < 25; vv++) {
                float m0 = Mb[(tb+0)*25 + vv];
                float m1 = Mb[(tb+1)*25 + vv];
                float m2 = Mb[(tb+2)*25 + vv];
                const float* sr = Sb + vv*25 + wb;
#pragma unroll
                for (int j = 0; j < 5; j++) {
                    float sv = sr[j];
                    acc[0][j] += m0 * sv;
                    acc[1][j] += m1 * sv;
                    acc[2][j] += m2 * sv;
                }
            }
        }
    }
    __syncthreads();
    if (act) {
#pragma unroll
        for (int i = 0; i < 3; i++)
#pragma unroll
            for (int j = 0; j < 5; j++)
                Ms[(tb+i)*25 + wb + j] = acc[i][j];
    }
    __syncthreads();
    float s = 0.f, s2 = 0.f;
    float* yp = g_y1 + (n*64 + o)*TV + t0*25;
    for (int i = tid; i < 1875; i += 128) {
        float u = Ms[i];
        yp[i] = u;
        s += u; s2 += u*u;
    }
    red[tid] = s; red[128 + tid] = s2;
    __syncthreads();
    for (int st = 64; st > 0; st >>= 1) {
        if (tid < st) {
            red[tid]       += red[tid + st];
            red[128 + tid] += red[128 + tid + st];
        }
        __syncthreads();
    }
    if (tid == 0) {
        g_pA_s[o*256 + n*4 + tc] = red[0];
        g_pA_q[o*256 + n*4 + tc] = red[128];
    }
}

// ---------------- BN finalize from partials -------------------------------
__global__ void k_bn_final(const float* __restrict__ g, const float* __restrict__ b,
                           const float* __restrict__ ps, const float* __restrict__ pq,
                           int npart, int which)
{
    int o = blockIdx.x;
    int tid = threadIdx.x;
    __shared__ float red[256];
    float s = 0.f, s2 = 0.f;
    for (int i = tid; i < npart; i += 128) {
        s  += ps[o*npart + i];
        s2 += pq[o*npart + i];
    }
    red[tid] = s; red[128 + tid] = s2;
    __syncthreads();
    for (int st = 64; st > 0; st >>= 1) {
        if (tid < st) {
            red[tid]       += red[tid + st];
            red[128 + tid] += red[128 + tid + st];
        }
        __syncthreads();
    }
    if (tid == 0) {
        const float cnt = (float)(NB*TV);
        float mean = red[0] / cnt;
        float var  = red[128] / cnt - mean*mean;
        float sc = g[o] * rsqrtf(var + BNEPS);
        g_stat[which*128 + o*2 + 0] = sc;
        g_stat[which*128 + o*2 + 1] = b[o] - mean*sc;
    }
}

// ============== tcn via mma.sync tf32 (m16n8k8) ===========================
// Key: p = t*25+v flattens the conv to 9 shifted reads (shift (kt-4)*25)
// of the position stream. Per CTA: 128 positions x 64 out-ch, K = 64cin x 9kt.
__global__ __launch_bounds__(256, 2) void k_tcn_mma(
    const float* __restrict__ x, const float* __restrict__ bt)
{
    extern __shared__ float sm[];
    float* Ys  = sm;                    // [64][328]
    float* Wfs = sm + 64*YW;            // 4096 floats (one kt slice)
    float* aux = Wfs + 4096;            // [0..63]=bt, [64..191]=bn1 stats
    int tid = threadIdx.x, w = tid >> 5, l = tid & 31;
    int tile = blockIdx.x, n = blockIdx.y;
    int p0 = tile * TILE_P;

    if (tid < 64)  aux[tid] = bt[tid];
    if (tid < 128) aux[64 + tid] = g_stat[tid];
    __syncthreads();

    // stage Ys with fused bn1+residual+relu, tf32-rounded
    for (int i = tid; i < 64*YW; i += 256) {
        int cin = i / YW, pl = i % YW;
        int pg = p0 - 100 + pl;
        float val = 0.f;
        if (pg >= 0 && pg < TV) {
            int idx = (n*64 + cin)*TV + pg;
            val = fmaxf(0.f, g_y1[idx]*aux[64 + cin*2] + aux[64 + cin*2 + 1] + x[idx]);
        }
        Ys[i] = tf32r(val);
    }

    float c[8][4];
#pragma unroll
    for (int nt = 0; nt < 8; nt++)
#pragma unroll
        for (int j = 0; j < 4; j++) c[nt][j] = 0.f;

    int rbase0 = w*16 + (l >> 2);
    int cbase  = l & 3;
#pragma unroll 1
    for (int kt = 0; kt < 9; kt++) {
        __syncthreads();
        for (int i = tid; i < 4096; i += 256) Wfs[i] = g_Wf[kt*4096 + i];
        __syncthreads();
        int rbase = rbase0 + kt*25;      // position row within Ys
#pragma unroll 1
        for (int s = 0; s < 8; s++) {
            const float* A0 = Ys + (s*8 + cbase)*YW + rbase;
            uint32_t a0 = __float_as_uint(A0[0]);
            uint32_t a1 = __float_as_uint(A0[8]);
            const float* A2 = A0 + 4*YW;
            uint32_t a2 = __float_as_uint(A2[0]);
            uint32_t a3 = __float_as_uint(A2[8]);
            const float2* B = (const float2*)Wfs + s*8*32 + l;
#pragma unroll
            for (int nt = 0; nt < 8; nt++) {
                float2 b = B[nt*32];
                mma_tf32(c[nt], a0, a1, a2, a3,
                         __float_as_uint(b.x), __float_as_uint(b.y));
            }
        }
    }
    __syncthreads();
    // epilogue: fragments -> smem transpose (+bias), partials, coalesced out
    float* Sout = sm;                   // [64][130], aliases Ys (done)
#pragma unroll
    for (int nt = 0; nt < 8; nt++) {
        int o = nt*8 + (l & 3)*2;
        int p = w*16 + (l >> 2);
        Sout[o*SOW + p]         = c[nt][0] + aux[o];
        Sout[(o+1)*SOW + p]     = c[nt][1] + aux[o+1];
        Sout[o*SOW + p + 8]     = c[nt][2] + aux[o];
        Sout[(o+1)*SOW + p + 8] = c[nt][3] + aux[o+1];
    }
    __syncthreads();
    if (tid < 64) {
        float s = 0.f, q = 0.f;
        int lim = TV - p0; if (lim > TILE_P) lim = TILE_P;
        for (int p = 0; p < lim; p++) {
            float u = Sout[tid*SOW + p];
            s += u; q += u*u;
        }
        int cta = n*NTILE + tile;
        g_pB_s[tid*NCTA_B + cta] = s;
        g_pB_q[tid*NCTA_B + cta] = q;
    }
    for (int i = tid; i < 8192; i += 256) {
        int o = i >> 7, p = i & 127;
        if (p0 + p < TV)
            g_y3[(n*64 + o)*TV + p0 + p] = Sout[o*SOW + p];
    }
}

// ---- final: out = relu(bn2(y3) + x), elementwise -------------------------
__global__ __launch_bounds__(256) void k_bn_apply(
    const float* __restrict__ x, float* __restrict__ out)
{
    for (long i = (long)blockIdx.x*256 + threadIdx.x; i < NCTV; i += (long)gridDim.x*256) {
        int o = (int)((i / TV) & 63);
        float sc = g_stat[128 + o*2 + 0];
        float sf = g_stat[128 + o*2 + 1];
        out[i] = fmaxf(0.f, g_y3[i]*sc + sf + x[i]);
    }
}

// ---------------- launch --------------------------------------------------
extern "C" void kernel_launch(void* const* d_in, const int* in_sizes, int n_in,
                              void* d_out, int out_size)
{
    const float* x    = (const float*)d_in[0];
    const float* adj  = (const float*)d_in[1];
    const float* PA   = (const float*)d_in[2];
    const float* Wa   = (const float*)d_in[3];
    const float* ba   = (const float*)d_in[4];
    const float* Wb   = (const float*)d_in[5];
    const float* bb   = (const float*)d_in[6];
    const float* Wd   = (const float*)d_in[7];
    const float* bd   = (const float*)d_in[8];
    const float* g1   = (const float*)d_in[9];
    const float* b1   = (const float*)d_in[10];
    const float* Wt   = (const float*)d_in[11];
    const float* bt   = (const float*)d_in[12];
    const float* g2   = (const float*)d_in[13];
    const float* b2   = (const float*)d_in[14];
    float* out = (float*)d_out;

    float *pAs, *pAq, *pBs, *pBq;
    cudaGetSymbolAddress((void**)&pAs, g_pA_s);
    cudaGetSymbolAddress((void**)&pAq, g_pA_q);
    cudaGetSymbolAddress((void**)&pBs, g_pB_s);
    cudaGetSymbolAddress((void**)&pBq, g_pB_q);

    const int tcn_smem = (64*YW + 4096 + 192) * 4;   // 101120 B
    static int smem_set = 0;
    if (!smem_set) {
        cudaFuncSetAttribute(k_tcn_mma,
                             cudaFuncAttributeMaxDynamicSharedMemorySize, tcn_smem);
        smem_set = 1;
    }

    k_prep_wt<<<72, 256>>>(Wt);

    dim3 gconv(30, NB, 3);
    k_conv_fab<<<gconv, 256>>>(x, Wa, ba, Wb, bb);
    k_conv_M<<<gconv, 256>>>(x, Wd);
    k_gram_part<<<dim3(NB, 3, 6), 128>>>();
    k_gram_final<<<dim3(NB, 3), 128>>>(adj, PA);
    k_combine<<<dim3(4, OCH, NB), 128>>>(bd);

    k_bn_final<<<64, 128>>>(g1, b1, pAs, pAq, 256, 0);

    k_tcn_mma<<<dim3(NTILE, NB), 256, tcn_smem>>>(x, bt);

    k_bn_final<<<64, 128>>>(g2, b2, pBs, pBq, NCTA_B, 1);

    k_bn_apply<<<8192, 256>>>(x, out);

    // second tuple element: adj_mat passthrough
    long tail = (long)out_size - (long)NCTV;
    if (tail > 0) {
        long cnt = tail < 1875 ? tail : 1875;
        cudaMemcpyAsync(out + NCTV, d_in[1], cnt * sizeof(float),
                        cudaMemcpyDeviceToDevice);
    }
}

// round 6
// speedup vs baseline: 2.0247x; 1.4747x over previous
#include <cuda_runtime.h>
#include <math.h>
#include <stdint.h>

#define NB   64
#define CCH  64
#define TT   300
#define VV   25
#define ICH  16
#define OCH  64
#define KTAP 9
#define TV   (TT*VV)        /* 7500 */
#define CTV  (CCH*TV)       /* 480000 */
#define NCTV (NB*CTV)       /* 30720000 */
#define BNEPS 1e-5f

#define TILE_P 128
#define NTILE  59           /* ceil(7500/128) */
#define NCTA_B (NB*NTILE)   /* 3776 */
#define YW 328              /* tcn halo width; 328%32==8 -> cf LDS */
#define SOW 130

#define AW 136              /* conv A-tile stride; 136%32==8 */
#define EW 132              /* conv epilogue stride */

__device__ __forceinline__ float tf32r(float v) {
    float o; asm("cvt.rna.tf32.f32 %0, %1;" : "=f"(o) : "f"(v)); return o;
}
__device__ __forceinline__ void mma_tf32(float c[4], uint32_t a0, uint32_t a1,
                                         uint32_t a2, uint32_t a3,
                                         uint32_t b0, uint32_t b1) {
    asm volatile(
        "mma.sync.aligned.m16n8k8.row.col.f32.tf32.tf32.f32 "
        "{%0,%1,%2,%3}, {%4,%5,%6,%7}, {%8,%9}, {%0,%1,%2,%3};"
        : "+f"(c[0]), "+f"(c[1]), "+f"(c[2]), "+f"(c[3])
        : "r"(a0), "r"(a1), "r"(a2), "r"(a3), "r"(b0), "r"(b1));
}

// ---------------- scratch (device globals; no allocation) ----------------
__device__ float g_fab[3*NB*32*TV];        // fa(16)+fb(16) per k,n
__device__ float g_Sp[3*NB*6*625];         // gram partials
__device__ float g_S[3*NB*VV*VV];          // attention matrices
__device__ float g_M[3*NB*OCH*TV];         // M = Wd[k] @ x
__device__ float g_y1[NB*OCH*TV];          // gcn pre-BN
__device__ float g_y3[NB*OCH*TV];          // tcn output
__device__ float g_Wf[9*8*8*32*2];         // tcn packed tf32 B fragments
__device__ float g_Wpk[3*8*12*32*2];       // conv_all packed B frags
__device__ float g_pA_s[OCH*256];          // BN1 partials
__device__ float g_pA_q[OCH*256];
__device__ float g_pB_s[OCH*NCTA_B];       // BN2 partials
__device__ float g_pB_q[OCH*NCTA_B];
__device__ float g_stat[2*OCH*2];          // [which][o][{scale,shift}]

// ---- Wt -> per-lane packed tf32 B fragments: [kt][s][nt][lane][2] -------
__global__ void k_prep_wt(const float* __restrict__ Wt)
{
    int j = blockIdx.x*256 + threadIdx.x;
    if (j >= 9*8*8*32) return;
    int l  = j & 31;
    int nt = (j >> 5) & 7;
    int s  = (j >> 8) & 7;
    int kt = j >> 11;
    int cin = s*8 + (l & 3);
    int o   = nt*8 + (l >> 2);
    g_Wf[j*2 + 0] = tf32r(Wt[(o*64 + cin)*9 + kt]);
    g_Wf[j*2 + 1] = tf32r(Wt[(o*64 + cin + 4)*9 + kt]);
}

// ---- pack Wd/Wa/Wb into conv_all B frags: [g][s][nt][lane][2] -----------
__device__ __forceinline__ float conv_w(int j, int c,
    const float* Wd, const float* Wa, const float* Wb)
{
    if (j < 192) {
        int k = j >> 6, o = j & 63;
        return Wd[(k*64 + o)*64 + c];
    }
    int jj = j - 192;
    int k = jj >> 5, ch = jj & 31;
    return (ch < 16) ? Wa[(k*16 + ch)*64 + c] : Wb[(k*16 + ch - 16)*64 + c];
}

__global__ void k_prep_w_all(const float* __restrict__ Wd,
                             const float* __restrict__ Wa,
                             const float* __restrict__ Wb)
{
    int i = blockIdx.x*256 + threadIdx.x;
    if (i >= 3*8*12*32) return;
    int l  = i & 31;
    int nt = (i >> 5) % 12;
    int s  = (i / (32*12)) & 7;
    int g  = i / (32*12*8);
    int j  = g*96 + nt*8 + (l >> 2);
    int c  = s*8 + (l & 3);
    g_Wpk[i*2 + 0] = tf32r(conv_w(j, c,     Wd, Wa, Wb));
    g_Wpk[i*2 + 1] = tf32r(conv_w(j, c + 4, Wd, Wa, Wb));
}

// ============ fused 1x1 convs (M + fa/fb) via mma.sync tf32 ==============
// per CTA (tile,n): A = x[n] tile [64c][128p]; 288 outputs in 3 groups of 96
__global__ __launch_bounds__(256, 2) void k_conv_all(
    const float* __restrict__ x, const float* __restrict__ ba,
    const float* __restrict__ bb)
{
    extern __shared__ float sm[];
    float* As = sm;                  // [64][AW]
    float* E  = sm + 64*AW;          // [96][EW]
    float* bsm = E + 96*EW;          // [96] fab biases
    int tid = threadIdx.x, w = tid >> 5, l = tid & 31;
    int tile = blockIdx.x, n = blockIdx.y;
    int p0 = tile * TILE_P;

    if (tid < 96) {
        int k = tid >> 5, ch = tid & 31;
        bsm[tid] = (ch < 16) ? ba[k*16 + ch] : bb[k*16 + ch - 16];
    }
    // stage A (x already channel-major, positions contiguous)
    for (int i = tid; i < 64*128; i += 256) {
        int c = i >> 7, p = i & 127;
        int pg = p0 + p;
        As[c*AW + p] = (pg < TV) ? tf32r(x[(n*64 + c)*TV + pg]) : 0.f;
    }
    __syncthreads();

    int row = w*16 + (l >> 2);
    int cq  = l & 3;
    int lim = TV - p0; if (lim > TILE_P) lim = TILE_P;

#pragma unroll 1
    for (int g = 0; g < 3; g++) {
        float c[12][4];
#pragma unroll
        for (int nt = 0; nt < 12; nt++)
#pragma unroll
            for (int j = 0; j < 4; j++) c[nt][j] = 0.f;
#pragma unroll
        for (int s = 0; s < 8; s++) {
            const float* A0 = As + (s*8 + cq)*AW + row;
            uint32_t a0 = __float_as_uint(A0[0]);
            uint32_t a1 = __float_as_uint(A0[8]);
            const float* A2 = A0 + 4*AW;
            uint32_t a2 = __float_as_uint(A2[0]);
            uint32_t a3 = __float_as_uint(A2[8]);
            const float2* B = (const float2*)g_Wpk + (g*8 + s)*12*32 + l;
#pragma unroll
            for (int nt = 0; nt < 12; nt++) {
                float2 b = B[nt*32];
                mma_tf32(c[nt], a0, a1, a2, a3,
                         __float_as_uint(b.x), __float_as_uint(b.y));
            }
        }
        __syncthreads();   // E free (prev group stored)
#pragma unroll
        for (int nt = 0; nt < 12; nt++) {
            int jl = nt*8 + (l & 3)*2;
            int p  = w*16 + (l >> 2);
            E[jl*EW + p]           = c[nt][0];
            E[(jl+1)*EW + p]       = c[nt][1];
            E[jl*EW + p + 8]       = c[nt][2];
            E[(jl+1)*EW + p + 8]   = c[nt][3];
        }
        __syncthreads();
        for (int i = tid; i < 96*128; i += 256) {
            int jl = i >> 7, p = i & 127;
            if (p >= lim) continue;
            int j = g*96 + jl;
            float val = E[jl*EW + p];
            if (j < 192) {
                int k = j >> 6, o = j & 63;
                g_M[((k*NB + n)*64 + o)*TV + p0 + p] = val;
            } else {
                int jj = j - 192;
                int k = jj >> 5, ch = jj & 31;
                g_fab[(k*NB + n)*32*TV + ch*TV + p0 + p] = val + bsm[jj];
            }
        }
    }
}

// ---------------- gram partial: 25x25 over (16 o, 50 t) per block ---------
__global__ __launch_bounds__(128) void k_gram_part()
{
    int n = blockIdx.x, k = blockIdx.y, tc = blockIdx.z;
    int t0 = tc * 50;
    int tid = threadIdx.x;
    __shared__ float fas[1250], fbs[1250];
    const float* fa = g_fab + (k*NB + n)*32*TV;
    const float* fb = fa + 16*TV;
    int v = tid / 5, wq = tid % 5;
    bool act = tid < 125;
    float acc[5] = {0.f, 0.f, 0.f, 0.f, 0.f};
    for (int o = 0; o < 16; o++) {
        for (int i = tid; i < 1250; i += 128) {
            fas[i] = fa[o*TV + t0*25 + i];
            fbs[i] = fb[o*TV + t0*25 + i];
        }
        __syncthreads();
        if (act) {
#pragma unroll 5
            for (int tt = 0; tt < 50; tt++) {
                float m = fas[tt*25 + v];
                const float* fr = fbs + tt*25 + wq*5;
#pragma unroll
                for (int j = 0; j < 5; j++) acc[j] += m * fr[j];
            }
        }
        __syncthreads();
    }
    if (act) {
        float* sp = g_Sp + ((k*NB + n)*6 + tc)*625 + v*25 + wq*5;
#pragma unroll
        for (int j = 0; j < 5; j++) sp[j] = acc[j];
    }
}

// ---------------- gram finalize: reduce partials + softmax + A ------------
__global__ __launch_bounds__(128) void k_gram_final(
    const float* __restrict__ adj, const float* __restrict__ PA)
{
    int n = blockIdx.x, k = blockIdx.y;
    int tid = threadIdx.x;
    __shared__ float Ss[625];
    const float* sp = g_Sp + (k*NB + n)*6*625;
    for (int i = tid; i < 625; i += 128) {
        float s = 0.f;
#pragma unroll
        for (int p = 0; p < 6; p++) s += sp[p*625 + i];
        Ss[i] = s * (1.f / 4800.f);
    }
    __syncthreads();
    if (tid < 25) {
        int ww = tid;
        float m = -1e30f;
        for (int vv = 0; vv < 25; vv++) m = fmaxf(m, Ss[vv*25 + ww]);
        float s = 0.f;
        for (int vv = 0; vv < 25; vv++) s += expf(Ss[vv*25 + ww] - m);
        float inv = 1.f / s;
        float* Sp = g_S + (k*NB + n)*625;
        for (int vv = 0; vv < 25; vv++)
            Sp[vv*25 + ww] = expf(Ss[vv*25 + ww] - m)*inv
                           + adj[k*625 + vv*25 + ww] + PA[k*625 + vv*25 + ww];
    }
}

// ---- y1 = sum_k sum_v M*S + bd (+BN1 partials) ---------------------------
__global__ __launch_bounds__(128) void k_combine(const float* __restrict__ bd)
{
    int tc = blockIdx.x, o = blockIdx.y, n = blockIdx.z;
    int t0 = tc * 75;
    __shared__ float Ms[3*1875];
    __shared__ float Ssh[3*625];
    __shared__ float red[256];
    int tid = threadIdx.x;
    for (int i = tid; i < 1875; i += 128) {
        int kk = i / 625, r = i % 625;
        Ssh[i] = g_S[(kk*NB + n)*625 + r];
    }
#pragma unroll
    for (int kk = 0; kk < 3; kk++)
        for (int i = tid; i < 1875; i += 128)
            Ms[kk*1875 + i] = g_M[((kk*NB + n)*64 + o)*TV + t0*25 + i];
    __syncthreads();
    float bds = bd[o] + bd[64 + o] + bd[128 + o];
    float acc[3][5];
    int wq = tid % 5, tq = tid / 5;
    int tb = tq * 3, wb = wq * 5;
    bool act = tid < 125;
#pragma unroll
    for (int i = 0; i < 3; i++)
#pragma unroll
        for (int j = 0; j < 5; j++) acc[i][j] = bds;
    if (act) {
#pragma unroll
        for (int kk = 0; kk < 3; kk++) {
            const float* Mb = Ms + kk*1875;
            const float* Sb = Ssh + kk*625;
            for (int vv = 0; vv < 25; vv++) {
                float m0 = Mb[(tb+0)*25 + vv];
                float m1 = Mb[(tb+1)*25 + vv];
                float m2 = Mb[(tb+2)*25 + vv];
                const float* sr = Sb + vv*25 + wb;
#pragma unroll
                for (int j = 0; j < 5; j++) {
                    float sv = sr[j];
                    acc[0][j] += m0 * sv;
                    acc[1][j] += m1 * sv;
                    acc[2][j] += m2 * sv;
                }
            }
        }
    }
    __syncthreads();
    if (act) {
#pragma unroll
        for (int i = 0; i < 3; i++)
#pragma unroll
            for (int j = 0; j < 5; j++)
                Ms[(tb+i)*25 + wb + j] = acc[i][j];
    }
    __syncthreads();
    float s = 0.f, s2 = 0.f;
    float* yp = g_y1 + (n*64 + o)*TV + t0*25;
    for (int i = tid; i < 1875; i += 128) {
        float u = Ms[i];
        yp[i] = u;
        s += u; s2 += u*u;
    }
    red[tid] = s; red[128 + tid] = s2;
    __syncthreads();
    for (int st = 64; st > 0; st >>= 1) {
        if (tid < st) {
            red[tid]       += red[tid + st];
            red[128 + tid] += red[128 + tid + st];
        }
        __syncthreads();
    }
    if (tid == 0) {
        g_pA_s[o*256 + n*4 + tc] = red[0];
        g_pA_q[o*256 + n*4 + tc] = red[128];
    }
}

// ---------------- BN finalize from partials -------------------------------
__global__ void k_bn_final(const float* __restrict__ g, const float* __restrict__ b,
                           const float* __restrict__ ps, const float* __restrict__ pq,
                           int npart, int which)
{
    int o = blockIdx.x;
    int tid = threadIdx.x;
    __shared__ float red[256];
    float s = 0.f, s2 = 0.f;
    for (int i = tid; i < npart; i += 128) {
        s  += ps[o*npart + i];
        s2 += pq[o*npart + i];
    }
    red[tid] = s; red[128 + tid] = s2;
    __syncthreads();
    for (int st = 64; st > 0; st >>= 1) {
        if (tid < st) {
            red[tid]       += red[tid + st];
            red[128 + tid] += red[128 + tid + st];
        }
        __syncthreads();
    }
    if (tid == 0) {
        const float cnt = (float)(NB*TV);
        float mean = red[0] / cnt;
        float var  = red[128] / cnt - mean*mean;
        float sc = g[o] * rsqrtf(var + BNEPS);
        g_stat[which*128 + o*2 + 0] = sc;
        g_stat[which*128 + o*2 + 1] = b[o] - mean*sc;
    }
}

// ============== tcn via mma.sync tf32 (m16n8k8) ===========================
__global__ __launch_bounds__(256, 2) void k_tcn_mma(
    const float* __restrict__ x, const float* __restrict__ bt)
{
    extern __shared__ float sm[];
    float* Ys  = sm;                    // [64][328]
    float* Wfs = sm + 64*YW;            // 4096 floats (one kt slice)
    float* aux = Wfs + 4096;            // [0..63]=bt, [64..191]=bn1 stats
    int tid = threadIdx.x, w = tid >> 5, l = tid & 31;
    int tile = blockIdx.x, n = blockIdx.y;
    int p0 = tile * TILE_P;

    if (tid < 64)  aux[tid] = bt[tid];
    if (tid < 128) aux[64 + tid] = g_stat[tid];
    __syncthreads();

    for (int i = tid; i < 64*YW; i += 256) {
        int cin = i / YW, pl = i % YW;
        int pg = p0 - 100 + pl;
        float val = 0.f;
        if (pg >= 0 && pg < TV) {
            int idx = (n*64 + cin)*TV + pg;
            val = fmaxf(0.f, g_y1[idx]*aux[64 + cin*2] + aux[64 + cin*2 + 1] + x[idx]);
        }
        Ys[i] = tf32r(val);
    }

    float c[8][4];
#pragma unroll
    for (int nt = 0; nt < 8; nt++)
#pragma unroll
        for (int j = 0; j < 4; j++) c[nt][j] = 0.f;

    int rbase0 = w*16 + (l >> 2);
    int cbase  = l & 3;
#pragma unroll 1
    for (int kt = 0; kt < 9; kt++) {
        __syncthreads();
        for (int i = tid; i < 4096; i += 256) Wfs[i] = g_Wf[kt*4096 + i];
        __syncthreads();
        int rbase = rbase0 + kt*25;
#pragma unroll 1
        for (int s = 0; s < 8; s++) {
            const float* A0 = Ys + (s*8 + cbase)*YW + rbase;
            uint32_t a0 = __float_as_uint(A0[0]);
            uint32_t a1 = __float_as_uint(A0[8]);
            const float* A2 = A0 + 4*YW;
            uint32_t a2 = __float_as_uint(A2[0]);
            uint32_t a3 = __float_as_uint(A2[8]);
            const float2* B = (const float2*)Wfs + s*8*32 + l;
#pragma unroll
            for (int nt = 0; nt < 8; nt++) {
                float2 b = B[nt*32];
                mma_tf32(c[nt], a0, a1, a2, a3,
                         __float_as_uint(b.x), __float_as_uint(b.y));
            }
        }
    }
    __syncthreads();
    float* Sout = sm;                   // [64][130]
#pragma unroll
    for (int nt = 0; nt < 8; nt++) {
        int o = nt*8 + (l & 3)*2;
        int p = w*16 + (l >> 2);
        Sout[o*SOW + p]         = c[nt][0] + aux[o];
        Sout[(o+1)*SOW + p]     = c[nt][1] + aux[o+1];
        Sout[o*SOW + p + 8]     = c[nt][2] + aux[o];
        Sout[(o+1)*SOW + p + 8] = c[nt][3] + aux[o+1];
    }
    __syncthreads();
    if (tid < 64) {
        float s = 0.f, q = 0.f;
        int lim = TV - p0; if (lim > TILE_P) lim = TILE_P;
        for (int p = 0; p < lim; p++) {
            float u = Sout[tid*SOW + p];
            s += u; q += u*u;
        }
        int cta = n*NTILE + tile;
        g_pB_s[tid*NCTA_B + cta] = s;
        g_pB_q[tid*NCTA_B + cta] = q;
    }
    for (int i = tid; i < 8192; i += 256) {
        int o = i >> 7, p = i & 127;
        if (p0 + p < TV)
            g_y3[(n*64 + o)*TV + p0 + p] = Sout[o*SOW + p];
    }
}

// ---- final: out = relu(bn2(y3) + x), elementwise -------------------------
__global__ __launch_bounds__(256) void k_bn_apply(
    const float* __restrict__ x, float* __restrict__ out)
{
    for (long i = (long)blockIdx.x*256 + threadIdx.x; i < NCTV; i += (long)gridDim.x*256) {
        int o = (int)((i / TV) & 63);
        float sc = g_stat[128 + o*2 + 0];
        float sf = g_stat[128 + o*2 + 1];
        out[i] = fmaxf(0.f, g_y3[i]*sc + sf + x[i]);
    }
}

// ---------------- launch --------------------------------------------------
extern "C" void kernel_launch(void* const* d_in, const int* in_sizes, int n_in,
                              void* d_out, int out_size)
{
    const float* x    = (const float*)d_in[0];
    const float* adj  = (const float*)d_in[1];
    const float* PA   = (const float*)d_in[2];
    const float* Wa   = (const float*)d_in[3];
    const float* ba   = (const float*)d_in[4];
    const float* Wb   = (const float*)d_in[5];
    const float* bb   = (const float*)d_in[6];
    const float* Wd   = (const float*)d_in[7];
    const float* bd   = (const float*)d_in[8];
    const float* g1   = (const float*)d_in[9];
    const float* b1   = (const float*)d_in[10];
    const float* Wt   = (const float*)d_in[11];
    const float* bt   = (const float*)d_in[12];
    const float* g2   = (const float*)d_in[13];
    const float* b2   = (const float*)d_in[14];
    float* out = (float*)d_out;

    float *pAs, *pAq, *pBs, *pBq;
    cudaGetSymbolAddress((void**)&pAs, g_pA_s);
    cudaGetSymbolAddress((void**)&pAq, g_pA_q);
    cudaGetSymbolAddress((void**)&pBs, g_pB_s);
    cudaGetSymbolAddress((void**)&pBq, g_pB_q);

    const int tcn_smem  = (64*YW + 4096 + 192) * 4;     // 101120 B
    const int conv_smem = (64*AW + 96*EW + 96) * 4;     // 85888 B
    static int smem_set = 0;
    if (!smem_set) {
        cudaFuncSetAttribute(k_tcn_mma,
                             cudaFuncAttributeMaxDynamicSharedMemorySize, tcn_smem);
        cudaFuncSetAttribute(k_conv_all,
                             cudaFuncAttributeMaxDynamicSharedMemorySize, conv_smem);
        smem_set = 1;
    }

    k_prep_wt<<<72, 256>>>(Wt);
    k_prep_w_all<<<36, 256>>>(Wd, Wa, Wb);

    k_conv_all<<<dim3(NTILE, NB), 256, conv_smem>>>(x, ba, bb);
    k_gram_part<<<dim3(NB, 3, 6), 128>>>();
    k_gram_final<<<dim3(NB, 3), 128>>>(adj, PA);
    k_combine<<<dim3(4, OCH, NB), 128>>>(bd);

    k_bn_final<<<64, 128>>>(g1, b1, pAs, pAq, 256, 0);

    k_tcn_mma<<<dim3(NTILE, NB), 256, tcn_smem>>>(x, bt);

    k_bn_final<<<64, 128>>>(g2, b2, pBs, pBq, NCTA_B, 1);

    k_bn_apply<<<8192, 256>>>(x, out);

    // second tuple element: adj_mat passthrough
    long tail = (long)out_size - (long)NCTV;
    if (tail > 0) {
        long cnt = tail < 1875 ? tail : 1875;
        cudaMemcpyAsync(out + NCTV, d_in[1], cnt * sizeof(float),
                        cudaMemcpyDeviceToDevice);
    }
}